// round 1
// baseline (speedup 1.0000x reference)
#include <cuda_runtime.h>
#include <math_constants.h>

#define B_   4
#define C2_  64
#define C_   128
#define N_   4096

// Scratch (allocation-free rule: __device__ globals)
__device__ float g_K[B_*C2_*N_];  // theta(concat(H,L))  -> keys   [b][c][n]
__device__ float g_Q[B_*C2_*N_];  // phi(concat(H,L))    -> queries[b][c][m]
__device__ float g_V[B_*C2_*N_];  // g(L)                -> values [b][c][n]
__device__ float g_E[B_*C2_*N_];  // attention output    [b][c][n]

// ---- packed f32x2 helpers (Blackwell FFMA2 path) ----
__device__ __forceinline__ unsigned long long pk2(float x, float y) {
    unsigned long long r;
    asm("mov.b64 %0, {%1,%2};" : "=l"(r) : "f"(x), "f"(y));
    return r;
}
__device__ __forceinline__ float2 upk2(unsigned long long v) {
    float2 f;
    asm("mov.b64 {%0,%1}, %2;" : "=f"(f.x), "=f"(f.y) : "l"(v));
    return f;
}
__device__ __forceinline__ void fma2(unsigned long long &d, unsigned long long a, unsigned long long b) {
    asm("fma.rn.f32x2 %0, %1, %2, %0;" : "+l"(d) : "l"(a), "l"(b));
}

// ============================================================
// Kernel 1: 1x1 conv projections as GEMMs.
//   proj 0: g_K = theta_w[64,128] @ concat(H,L) + theta_b
//   proj 1: g_Q = phi_w  [64,128] @ concat(H,L) + phi_b
//   proj 2: g_V = g_w    [64, 64] @ L           + g_b
// grid (32 pixel-tiles, 3 projs, 4 batch), 256 threads.
// ============================================================
__global__ void __launch_bounds__(256) proj_kernel(
    const float* __restrict__ Hp, const float* __restrict__ Lp,
    const float* __restrict__ tw, const float* __restrict__ tb,
    const float* __restrict__ pw, const float* __restrict__ pb,
    const float* __restrict__ gw, const float* __restrict__ gb)
{
    extern __shared__ float sm[];
    float* sX = sm;              // [IC][128]
    float* sW = sm + 128 * 128;  // [64][IC]

    const int proj = blockIdx.y;
    const int b    = blockIdx.z;
    const int p0   = blockIdx.x << 7;
    const int tid  = threadIdx.x;

    const float* W; const float* bias; float* dst; int IC;
    if (proj == 0)      { W = tw; bias = tb; dst = g_K; IC = C_;  }
    else if (proj == 1) { W = pw; bias = pb; dst = g_Q; IC = C_;  }
    else                { W = gw; bias = gb; dst = g_V; IC = C2_; }

    for (int i = tid; i < IC * 128; i += 256) {
        int c = i >> 7, p = i & 127;
        const float* src = (proj == 2) ? Lp : ((c < 64) ? Hp : Lp);
        sX[i] = src[(((b << 6) + (c & 63)) << 12) + p0 + p];
    }
    for (int i = tid; i < 64 * IC; i += 256) sW[i] = W[i];
    __syncthreads();

    const int to = tid >> 4;   // output-channel group (4 ch)
    const int tp = tid & 15;   // pixel-pair group

    unsigned long long acc[4][4];
    #pragma unroll
    for (int i = 0; i < 4; i++)
        #pragma unroll
        for (int j = 0; j < 4; j++) acc[i][j] = 0ULL;

    for (int c = 0; c < IC; c++) {
        unsigned long long wv[4], x2[4];
        #pragma unroll
        for (int i = 0; i < 4; i++) {
            float w = sW[(4 * to + i) * IC + c];
            wv[i] = pk2(w, w);
        }
        #pragma unroll
        for (int j = 0; j < 4; j++)
            x2[j] = *(const unsigned long long*)&sX[(c << 7) + 2 * tp + (j << 5)];
        #pragma unroll
        for (int i = 0; i < 4; i++)
            #pragma unroll
            for (int j = 0; j < 4; j++) fma2(acc[i][j], wv[i], x2[j]);
    }

    #pragma unroll
    for (int i = 0; i < 4; i++) {
        int o = 4 * to + i;
        float bo = bias[o];
        #pragma unroll
        for (int j = 0; j < 4; j++) {
            float2 r = upk2(acc[i][j]);
            r.x += bo; r.y += bo;
            *(float2*)&dst[(((b << 6) + o) << 12) + p0 + 2 * tp + (j << 5)] = r;
        }
    }
}

// ============================================================
// Kernel 2: fused attention (flash-style, softmax over keys n).
//   S[n,m] = sum_c K[c,n]*Q[c,m]   (unscaled)
//   P      = softmax_n(S)          (online)
//   E[c,m] = sum_n V[c,n]*P[n,m], finally / rowsum
// grid (32 query-tiles, 4 batch), 256 threads, one block per SM.
// ============================================================
__global__ void __launch_bounds__(256, 1) attn_kernel()
{
    extern __shared__ float sm[];
    float* sQ = sm;                 // [64][128]
    float* sK = sm + 8192;          // [64][128]
    float* sV = sm + 16384;         // [64][128]
    float* sP = sm + 24576;         // [128][130] (pad kills bank conflicts)
    float* sAlpha = sm + 24576 + 128 * 130;  // [128]
    float* sSum   = sAlpha + 128;            // [128]

    const int tid = threadIdx.x;
    const int b   = blockIdx.y;
    const int m0  = blockIdx.x << 7;

    // Load Q tile once
    for (int i = tid; i < 8192; i += 256) {
        int c = i >> 7, m = i & 127;
        sQ[i] = g_Q[(((b << 6) + c) << 12) + m0 + m];
    }

    // S-phase mapping: n = tn + 16*ii (ii 0..7), m pairs = 2*tm + 32*jj (jj 0..3)
    const int tn = tid & 15, tm = tid >> 4;
    // E-phase mapping: c = 4*cg + i, m pairs = 2*mg + 32*jj
    const int cg = tid >> 4, mg = tid & 15;

    float2 mr[4], lr[4];
    #pragma unroll
    for (int j = 0; j < 4; j++) {
        mr[j] = make_float2(-CUDART_INF_F, -CUDART_INF_F);
        lr[j] = make_float2(0.f, 0.f);
    }
    unsigned long long e2[4][4];
    #pragma unroll
    for (int i = 0; i < 4; i++)
        #pragma unroll
        for (int j = 0; j < 4; j++) e2[i][j] = 0ULL;

    for (int kt = 0; kt < 32; kt++) {
        const int n0 = kt << 7;
        __syncthreads();  // previous E-phase finished with sK/sV/sP
        for (int i = tid; i < 8192; i += 256) {
            int c = i >> 7, n = i & 127;
            int gi = (((b << 6) + c) << 12) + n0 + n;
            sK[i] = g_K[gi];
            sV[i] = g_V[gi];
        }
        __syncthreads();

        // ---- S = K^T Q over this tile ----
        unsigned long long s2[8][4];
        #pragma unroll
        for (int ii = 0; ii < 8; ii++)
            #pragma unroll
            for (int jj = 0; jj < 4; jj++) s2[ii][jj] = 0ULL;

        for (int c = 0; c < 64; c++) {
            unsigned long long kk[8], q2[4];
            #pragma unroll
            for (int ii = 0; ii < 8; ii++) {
                float k = sK[(c << 7) + tn + (ii << 4)];
                kk[ii] = pk2(k, k);
            }
            #pragma unroll
            for (int jj = 0; jj < 4; jj++)
                q2[jj] = *(const unsigned long long*)&sQ[(c << 7) + 2 * tm + (jj << 5)];
            #pragma unroll
            for (int ii = 0; ii < 8; ii++)
                #pragma unroll
                for (int jj = 0; jj < 4; jj++) fma2(s2[ii][jj], kk[ii], q2[jj]);
        }

        // ---- online softmax over n (column reduce across tn lanes) ----
        #pragma unroll
        for (int jj = 0; jj < 4; jj++) {
            float2 cm = upk2(s2[0][jj]);
            #pragma unroll
            for (int ii = 1; ii < 8; ii++) {
                float2 f = upk2(s2[ii][jj]);
                cm.x = fmaxf(cm.x, f.x); cm.y = fmaxf(cm.y, f.y);
            }
            #pragma unroll
            for (int off = 1; off < 16; off <<= 1) {
                cm.x = fmaxf(cm.x, __shfl_xor_sync(0xffffffffu, cm.x, off));
                cm.y = fmaxf(cm.y, __shfl_xor_sync(0xffffffffu, cm.y, off));
            }
            float2 mo = mr[jj];
            float2 mn = make_float2(fmaxf(mo.x, cm.x), fmaxf(mo.y, cm.y));
            float2 al = make_float2(__expf(mo.x - mn.x), __expf(mo.y - mn.y));
            float2 cs = make_float2(0.f, 0.f);
            #pragma unroll
            for (int ii = 0; ii < 8; ii++) {
                float2 f = upk2(s2[ii][jj]);
                float2 p = make_float2(__expf(f.x - mn.x), __expf(f.y - mn.y));
                cs.x += p.x; cs.y += p.y;
                *(float2*)&sP[(tn + (ii << 4)) * 130 + 2 * tm + (jj << 5)] = p;
            }
            #pragma unroll
            for (int off = 1; off < 16; off <<= 1) {
                cs.x += __shfl_xor_sync(0xffffffffu, cs.x, off);
                cs.y += __shfl_xor_sync(0xffffffffu, cs.y, off);
            }
            lr[jj].x = lr[jj].x * al.x + cs.x;
            lr[jj].y = lr[jj].y * al.y + cs.y;
            mr[jj] = mn;
            if (tn == 0) *(float2*)&sAlpha[2 * tm + (jj << 5)] = al;
        }
        __syncthreads();

        // ---- E = E*alpha + V @ P ----
        #pragma unroll
        for (int jj = 0; jj < 4; jj++) {
            float2 al = *(const float2*)&sAlpha[2 * mg + (jj << 5)];
            #pragma unroll
            for (int i = 0; i < 4; i++) {
                float2 f = upk2(e2[i][jj]);
                f.x *= al.x; f.y *= al.y;
                e2[i][jj] = pk2(f.x, f.y);
            }
        }
        for (int n = 0; n < 128; n++) {
            unsigned long long vv[4], p2[4];
            #pragma unroll
            for (int i = 0; i < 4; i++) {
                float v = sV[((4 * cg + i) << 7) + n];
                vv[i] = pk2(v, v);
            }
            #pragma unroll
            for (int jj = 0; jj < 4; jj++)
                p2[jj] = *(const unsigned long long*)&sP[n * 130 + 2 * mg + (jj << 5)];
            #pragma unroll
            for (int i = 0; i < 4; i++)
                #pragma unroll
                for (int jj = 0; jj < 4; jj++) fma2(e2[i][jj], vv[i], p2[jj]);
        }
    }

    // finalize: divide by row sums, write E
    if (tn == 0) {
        #pragma unroll
        for (int jj = 0; jj < 4; jj++)
            *(float2*)&sSum[2 * tm + (jj << 5)] = lr[jj];
    }
    __syncthreads();
    #pragma unroll
    for (int jj = 0; jj < 4; jj++) {
        float2 s = *(const float2*)&sSum[2 * mg + (jj << 5)];
        float2 inv = make_float2(1.f / s.x, 1.f / s.y);
        #pragma unroll
        for (int i = 0; i < 4; i++) {
            float2 f = upk2(e2[i][jj]);
            f.x *= inv.x; f.y *= inv.y;
            *(float2*)&g_E[(((b << 6) + 4 * cg + i) << 12) + m0 + 2 * mg + (jj << 5)] = f;
        }
    }
}

// ============================================================
// Kernel 3: 3x3 conv (SAME) + BN(inference) + ReLU + residual.
// All weights staged in smem as [ic*9+kk][oc] (oc contiguous for f32x2).
// grid (32 row-strips, 4 batch), 128 threads = 2 rows x 64 cols, 1 px/thread.
// ============================================================
__global__ void __launch_bounds__(128, 1) conv_kernel(
    const float* __restrict__ Hp,
    const float* __restrict__ cw, const float* __restrict__ cb,
    const float* __restrict__ gamma, const float* __restrict__ beta,
    const float* __restrict__ mean,  const float* __restrict__ var,
    float* __restrict__ out)
{
    extern __shared__ float sW[];  // [64*9][64] = 147456 B
    const int tid = threadIdx.x;
    const int b   = blockIdx.y;
    const int y0  = blockIdx.x << 1;

    for (int i = tid; i < 64 * 64 * 9; i += 128) {
        int oc = i / 576;
        int rem = i - oc * 576;
        int ic = rem / 9;
        int kk = rem - ic * 9;
        sW[(ic * 9 + kk) * 64 + oc] = cw[i];
    }
    __syncthreads();

    const int y = y0 + (tid >> 6);
    const int x = tid & 63;

    unsigned long long acc2[32];
    #pragma unroll
    for (int i = 0; i < 32; i++) acc2[i] = 0ULL;

    for (int ic = 0; ic < 64; ic++) {
        const float* src = &g_E[(((b << 6) + ic) << 12)];
        float in9[9];
        #pragma unroll
        for (int dy = 0; dy < 3; dy++) {
            int yy = y + dy - 1;
            bool yok = (yy >= 0) && (yy < 64);
            #pragma unroll
            for (int dx = 0; dx < 3; dx++) {
                int xx = x + dx - 1;
                bool ok = yok && (xx >= 0) && (xx < 64);
                in9[dy * 3 + dx] = ok ? src[(yy << 6) + xx] : 0.f;
            }
        }
        #pragma unroll
        for (int kk = 0; kk < 9; kk++) {
            unsigned long long iv = pk2(in9[kk], in9[kk]);
            const float* wrow = &sW[(ic * 9 + kk) << 6];
            #pragma unroll
            for (int q = 0; q < 16; q++) {
                ulonglong2 w = *(const ulonglong2*)&wrow[q << 2];
                fma2(acc2[2 * q],     iv, w.x);
                fma2(acc2[2 * q + 1], iv, w.y);
            }
        }
    }

    const int pix = (y << 6) + x;
    #pragma unroll
    for (int q = 0; q < 32; q++) {
        float2 f = upk2(acc2[q]);
        #pragma unroll
        for (int h = 0; h < 2; h++) {
            int oc = 2 * q + h;
            float v = (h ? f.y : f.x) + cb[oc];
            float scale = gamma[oc] * rsqrtf(var[oc] + 1e-5f);
            v = (v - mean[oc]) * scale + beta[oc];
            v = fmaxf(v, 0.f);
            int idx = (((b << 6) + oc) << 12) + pix;
            out[idx] = Hp[idx] + v;
        }
    }
}

// ============================================================
extern "C" void kernel_launch(void* const* d_in, const int* in_sizes, int n_in,
                              void* d_out, int out_size)
{
    const float* Hp    = (const float*)d_in[0];
    const float* Lp    = (const float*)d_in[1];
    const float* tw    = (const float*)d_in[2];
    const float* tb    = (const float*)d_in[3];
    const float* pw    = (const float*)d_in[4];
    const float* pb    = (const float*)d_in[5];
    const float* gw    = (const float*)d_in[6];
    const float* gb    = (const float*)d_in[7];
    const float* cw    = (const float*)d_in[8];
    const float* cb    = (const float*)d_in[9];
    const float* gamma = (const float*)d_in[10];
    const float* beta  = (const float*)d_in[11];
    const float* mean  = (const float*)d_in[12];
    const float* var   = (const float*)d_in[13];
    float* out = (float*)d_out;

    const int smem_proj = (128 * 128 + 64 * 128) * 4;            // 98304
    const int smem_attn = (24576 + 128 * 130 + 256) * 4;         // 165888
    const int smem_conv = 64 * 64 * 9 * 4;                       // 147456

    cudaFuncSetAttribute(proj_kernel, cudaFuncAttributeMaxDynamicSharedMemorySize, smem_proj);
    cudaFuncSetAttribute(attn_kernel, cudaFuncAttributeMaxDynamicSharedMemorySize, smem_attn);
    cudaFuncSetAttribute(conv_kernel, cudaFuncAttributeMaxDynamicSharedMemorySize, smem_conv);

    proj_kernel<<<dim3(32, 3, 4), 256, smem_proj>>>(Hp, Lp, tw, tb, pw, pb, gw, gb);
    attn_kernel<<<dim3(32, 4), 256, smem_attn>>>();
    conv_kernel<<<dim3(32, 4), 128, smem_conv>>>(Hp, cw, cb, gamma, beta, mean, var, out);
}